// round 2
// baseline (speedup 1.0000x reference)
#include <cuda_runtime.h>
#include <cuda_bf16.h>
#include <math.h>

#define B_ 2
#define T_ 1024
#define DM 3072
#define NH 32
#define NKV 8
#define HD 96

// ---------------- scratch (device globals; no allocation allowed) --------------
__device__ float g_q[B_ * T_ * NH * HD];    // [bt][h][d]
__device__ float g_k[B_ * T_ * NKV * HD];   // [bt][kvh][d]
__device__ float g_v[B_ * T_ * NKV * HD];
__device__ float g_o[B_ * T_ * NH * HD];    // attention output

// ---------------- SGEMM: C[M,N] = A[M,K] @ B[N,K]^T  (both row-major) ----------
// 128x128 tile, BK=16, 256 threads, 8x8 microtile split into 4x 4x4 quads.
#define BM 128
#define BN 128
#define BK 16

__global__ __launch_bounds__(256) void sgemm_tn(const float* __restrict__ A,
                                                const float* __restrict__ Bm,
                                                float* __restrict__ C,
                                                int M, int N, int K) {
    __shared__ float As[BK][BM];
    __shared__ float Bs[BK][BN];

    int tid = threadIdx.x;
    int tx = tid & 15;       // 0..15 (col quad)
    int ty = tid >> 4;       // 0..15 (row quad)
    int bm = blockIdx.y * BM;
    int bn = blockIdx.x * BN;

    int lr = tid >> 2;           // 0..63
    int lc = (tid & 3) * 4;      // 0,4,8,12

    const float* Ap = A + (bm + lr) * K + lc;
    const float* Bp = Bm + (bn + lr) * K + lc;

    float acc[8][8];
#pragma unroll
    for (int i = 0; i < 8; i++)
#pragma unroll
        for (int j = 0; j < 8; j++) acc[i][j] = 0.f;

    for (int k0 = 0; k0 < K; k0 += BK) {
        float4 a0 = *(const float4*)(Ap + k0);
        float4 a1 = *(const float4*)(Ap + 64 * K + k0);
        float4 b0 = *(const float4*)(Bp + k0);
        float4 b1 = *(const float4*)(Bp + 64 * K + k0);
        __syncthreads();
        As[lc + 0][lr] = a0.x; As[lc + 1][lr] = a0.y; As[lc + 2][lr] = a0.z; As[lc + 3][lr] = a0.w;
        As[lc + 0][lr + 64] = a1.x; As[lc + 1][lr + 64] = a1.y; As[lc + 2][lr + 64] = a1.z; As[lc + 3][lr + 64] = a1.w;
        Bs[lc + 0][lr] = b0.x; Bs[lc + 1][lr] = b0.y; Bs[lc + 2][lr] = b0.z; Bs[lc + 3][lr] = b0.w;
        Bs[lc + 0][lr + 64] = b1.x; Bs[lc + 1][lr + 64] = b1.y; Bs[lc + 2][lr + 64] = b1.z; Bs[lc + 3][lr + 64] = b1.w;
        __syncthreads();

#pragma unroll
        for (int kk = 0; kk < BK; kk++) {
            float ar[8], br[8];
            *(float4*)(ar)     = *(const float4*)&As[kk][ty * 4];
            *(float4*)(ar + 4) = *(const float4*)&As[kk][64 + ty * 4];
            *(float4*)(br)     = *(const float4*)&Bs[kk][tx * 4];
            *(float4*)(br + 4) = *(const float4*)&Bs[kk][64 + tx * 4];
#pragma unroll
            for (int i = 0; i < 8; i++)
#pragma unroll
                for (int j = 0; j < 8; j++) acc[i][j] = fmaf(ar[i], br[j], acc[i][j]);
        }
    }

#pragma unroll
    for (int ih = 0; ih < 2; ih++) {
#pragma unroll
        for (int i = 0; i < 4; i++) {
            int row = bm + ih * 64 + ty * 4 + i;
#pragma unroll
            for (int jh = 0; jh < 2; jh++) {
                float4 v = make_float4(acc[ih * 4 + i][jh * 4 + 0], acc[ih * 4 + i][jh * 4 + 1],
                                       acc[ih * 4 + i][jh * 4 + 2], acc[ih * 4 + i][jh * 4 + 3]);
                *(float4*)(C + row * N + bn + jh * 64 + tx * 4) = v;
            }
        }
    }
}

// ---------------- RMSNorm + RoPE (one warp per head-vector of 96) --------------
__global__ void norm_rope_kernel(float* __restrict__ buf, const float* __restrict__ w,
                                 const float* __restrict__ cs, const float* __restrict__ sn,
                                 int nheads) {
    int warp = (blockIdx.x * blockDim.x + threadIdx.x) >> 5;
    int lane = threadIdx.x & 31;
    int total = B_ * T_ * nheads;
    if (warp >= total) return;
    int head = warp % nheads;
    int bt = warp / nheads;
    int t = bt % T_;
    float* v = buf + (size_t)(bt * nheads + head) * HD;

    // lane owns pair p=lane (elems 2p,2p+1); lanes<16 also own pair 32+lane
    float x0 = v[2 * lane], x1 = v[2 * lane + 1];
    float y0 = 0.f, y1 = 0.f;
    if (lane < 16) { y0 = v[64 + 2 * lane]; y1 = v[65 + 2 * lane]; }
    float ss = x0 * x0 + x1 * x1 + y0 * y0 + y1 * y1;
#pragma unroll
    for (int o = 16; o; o >>= 1) ss += __shfl_xor_sync(0xffffffffu, ss, o);
    float r = rsqrtf(ss / 96.f + 1e-6f);

    const float* cr = cs + t * HD;
    const float* sr = sn + t * HD;
    {
        int e0 = 2 * lane, e1 = e0 + 1;
        float a = x0 * w[e0] * r, b = x1 * w[e1] * r;
        v[e0] = a * cr[e0] - b * sr[e0];
        v[e1] = a * sr[e1] + b * cr[e1];
    }
    if (lane < 16) {
        int e0 = 64 + 2 * lane, e1 = e0 + 1;
        float a = y0 * w[e0] * r, b = y1 * w[e1] * r;
        v[e0] = a * cr[e0] - b * sr[e0];
        v[e1] = a * sr[e1] + b * cr[e1];
    }
}

// ---------------- Flash attention (fp32, Br=Bc=64, online softmax) -------------
#define QK_STR 68    // Qs/Ks stored d-major: [96][64+pad]
#define V_STR 100    // Vs row-major: [64][96+pad]
#define P_STR 68     // Ps stored k-major: [64][64+pad]

__global__ __launch_bounds__(256) void flash_kernel(const float* __restrict__ Q,
                                                    const float* __restrict__ K,
                                                    const float* __restrict__ V,
                                                    float* __restrict__ O) {
    extern __shared__ float sm[];
    float* Qs = sm;                       // 96*68
    float* Ks = Qs + 96 * QK_STR;         // 96*68
    float* Vs = Ks + 96 * QK_STR;         // 64*100
    float* Ps = Vs + 64 * V_STR;          // 64*68  (k-major: Ps[k][row])

    int qt = blockIdx.x;                  // 0..15
    int bh = blockIdx.y;                  // b*32 + h
    int b = bh >> 5, h = bh & 31;
    int kvh = h >> 2;

    int tid = threadIdx.x;
    int tx = tid & 15, ty = tid >> 4;
    const float scale = 0.10206207261596575f;  // 1/sqrt(96)

    const float* Qg = Q + ((size_t)(b * T_ + qt * 64) * NH + h) * HD;
    const float* Kg = K + (size_t)b * T_ * NKV * HD + kvh * HD;
    const float* Vg = V + (size_t)b * T_ * NKV * HD + kvh * HD;

    // load Q tile (64x96), transposed to d-major, pre-scaled
    for (int i = tid; i < 64 * 24; i += 256) {
        int rrow = i / 24, c4 = (i % 24) * 4;
        float4 vq = *(const float4*)(Qg + (size_t)rrow * (NH * HD) + c4);
        Qs[(c4 + 0) * QK_STR + rrow] = vq.x * scale;
        Qs[(c4 + 1) * QK_STR + rrow] = vq.y * scale;
        Qs[(c4 + 2) * QK_STR + rrow] = vq.z * scale;
        Qs[(c4 + 3) * QK_STR + rrow] = vq.w * scale;
    }

    float mrow[4], lrow[4], oacc[4][6];
#pragma unroll
    for (int i = 0; i < 4; i++) {
        mrow[i] = -INFINITY; lrow[i] = 0.f;
#pragma unroll
        for (int j = 0; j < 6; j++) oacc[i][j] = 0.f;
    }
    int q_row0 = qt * 64;

    for (int jt = 0; jt <= qt; jt++) {
        __syncthreads();  // protect previous Ps/Vs reads and first-iter Q stores
        // load K (transposed) and V (row-major) tiles
        for (int i = tid; i < 64 * 24; i += 256) {
            int rrow = i / 24, c4 = (i % 24) * 4;
            float4 vk = *(const float4*)(Kg + (size_t)(jt * 64 + rrow) * (NKV * HD) + c4);
            Ks[(c4 + 0) * QK_STR + rrow] = vk.x;
            Ks[(c4 + 1) * QK_STR + rrow] = vk.y;
            Ks[(c4 + 2) * QK_STR + rrow] = vk.z;
            Ks[(c4 + 3) * QK_STR + rrow] = vk.w;
            float4 vv = *(const float4*)(Vg + (size_t)(jt * 64 + rrow) * (NKV * HD) + c4);
            *(float4*)(Vs + rrow * V_STR + c4) = vv;
        }
        __syncthreads();

        // S = Q @ K^T  (4x4 per thread: rows ty*4+i, cols tx*4+j)
        float s[4][4];
#pragma unroll
        for (int i = 0; i < 4; i++)
#pragma unroll
            for (int j = 0; j < 4; j++) s[i][j] = 0.f;
#pragma unroll 8
        for (int d = 0; d < 96; d++) {
            float4 aq = *(const float4*)(Qs + d * QK_STR + ty * 4);
            float4 bk = *(const float4*)(Ks + d * QK_STR + tx * 4);
            float ar[4] = {aq.x, aq.y, aq.z, aq.w};
            float br[4] = {bk.x, bk.y, bk.z, bk.w};
#pragma unroll
            for (int i = 0; i < 4; i++)
#pragma unroll
                for (int j = 0; j < 4; j++) s[i][j] = fmaf(ar[i], br[j], s[i][j]);
        }

        if (jt == qt) {
#pragma unroll
            for (int i = 0; i < 4; i++)
#pragma unroll
                for (int j = 0; j < 4; j++)
                    if (jt * 64 + tx * 4 + j > q_row0 + ty * 4 + i) s[i][j] = -INFINITY;
        }

        // online softmax per row (row split over 16 tx lanes)
#pragma unroll
        for (int i = 0; i < 4; i++) {
            float tm = fmaxf(fmaxf(s[i][0], s[i][1]), fmaxf(s[i][2], s[i][3]));
#pragma unroll
            for (int o = 8; o; o >>= 1) tm = fmaxf(tm, __shfl_xor_sync(0xffffffffu, tm, o));
            float nm = fmaxf(mrow[i], tm);
            float alpha = __expf(mrow[i] - nm);
            mrow[i] = nm;
            float rs = 0.f;
#pragma unroll
            for (int j = 0; j < 4; j++) { s[i][j] = __expf(s[i][j] - nm); rs += s[i][j]; }
#pragma unroll
            for (int o = 8; o; o >>= 1) rs += __shfl_xor_sync(0xffffffffu, rs, o);
            lrow[i] = lrow[i] * alpha + rs;
#pragma unroll
            for (int j = 0; j < 6; j++) oacc[i][j] *= alpha;
            // store P k-major: Ps[col][row]
#pragma unroll
            for (int j = 0; j < 4; j++)
                Ps[(tx * 4 + j) * P_STR + ty * 4 + i] = s[i][j];
        }
        __syncthreads();

        // O += P @ V   (rows ty*4+i, cols tx*6+j)
#pragma unroll 4
        for (int k = 0; k < 64; k++) {
            float4 p = *(const float4*)(Ps + k * P_STR + ty * 4);
            float2 v0 = *(const float2*)(Vs + k * V_STR + tx * 6);
            float2 v1 = *(const float2*)(Vs + k * V_STR + tx * 6 + 2);
            float2 v2 = *(const float2*)(Vs + k * V_STR + tx * 6 + 4);
            float pv[4] = {p.x, p.y, p.z, p.w};
            float vv[6] = {v0.x, v0.y, v1.x, v1.y, v2.x, v2.y};
#pragma unroll
            for (int i = 0; i < 4; i++)
#pragma unroll
                for (int j = 0; j < 6; j++) oacc[i][j] = fmaf(pv[i], vv[j], oacc[i][j]);
        }
    }

    // write out: O[b][q][h][:] normalized by l
#pragma unroll
    for (int i = 0; i < 4; i++) {
        float inv = 1.f / lrow[i];
        float* Og = O + ((size_t)(b * T_ + q_row0 + ty * 4 + i) * NH + h) * HD + tx * 6;
        float2 w0 = make_float2(oacc[i][0] * inv, oacc[i][1] * inv);
        float2 w1 = make_float2(oacc[i][2] * inv, oacc[i][3] * inv);
        float2 w2 = make_float2(oacc[i][4] * inv, oacc[i][5] * inv);
        *(float2*)(Og + 0) = w0;
        *(float2*)(Og + 2) = w1;
        *(float2*)(Og + 4) = w2;
    }
}

// ---------------- launch -------------------------------------------------------
extern "C" void kernel_launch(void* const* d_in, const int* in_sizes, int n_in,
                              void* d_out, int out_size) {
    const float* x   = (const float*)d_in[0];
    // d_in[1] = mask (causal; implemented directly in flash kernel)
    const float* wq  = (const float*)d_in[2];
    const float* wk  = (const float*)d_in[3];
    const float* wv  = (const float*)d_in[4];
    const float* wo  = (const float*)d_in[5];
    const float* qnw = (const float*)d_in[6];
    const float* knw = (const float*)d_in[7];
    const float* cs  = (const float*)d_in[8];
    const float* sn  = (const float*)d_in[9];
    float* out = (float*)d_out;

    float *q_buf, *k_buf, *v_buf, *o_buf;
    cudaGetSymbolAddress((void**)&q_buf, g_q);
    cudaGetSymbolAddress((void**)&k_buf, g_k);
    cudaGetSymbolAddress((void**)&v_buf, g_v);
    cudaGetSymbolAddress((void**)&o_buf, g_o);

    const int M = B_ * T_;  // 2048

    // QKV projections
    dim3 gq(DM / BN, M / BM);
    sgemm_tn<<<gq, 256>>>(x, wq, q_buf, M, DM, DM);
    dim3 gkv((NKV * HD) / BN, M / BM);
    sgemm_tn<<<gkv, 256>>>(x, wk, k_buf, M, NKV * HD, DM);
    sgemm_tn<<<gkv, 256>>>(x, wv, v_buf, M, NKV * HD, DM);

    // RMSNorm + RoPE
    {
        int warps_q = M * NH;
        norm_rope_kernel<<<(warps_q * 32 + 255) / 256, 256>>>(q_buf, qnw, cs, sn, NH);
        int warps_k = M * NKV;
        norm_rope_kernel<<<(warps_k * 32 + 255) / 256, 256>>>(k_buf, knw, cs, sn, NKV);
    }

    // Flash attention
    {
        size_t smem = (size_t)(96 * QK_STR * 2 + 64 * V_STR + 64 * P_STR) * sizeof(float);
        cudaFuncSetAttribute(flash_kernel, cudaFuncAttributeMaxDynamicSharedMemorySize, (int)smem);
        dim3 grid(T_ / 64, B_ * NH);
        flash_kernel<<<grid, 256, smem>>>(q_buf, k_buf, v_buf, o_buf);
    }

    // output projection
    sgemm_tn<<<gq, 256>>>(o_buf, wo, out, M, DM, DM);
}

// round 11
// speedup vs baseline: 1.5354x; 1.5354x over previous
#include <cuda_runtime.h>
#include <cuda_bf16.h>
#include <math.h>
#include <cstdint>

#define B_ 2
#define T_ 1024
#define DM 3072
#define NH 32
#define NKV 8
#define HD 96

// ---------------- scratch (device globals; no allocation allowed) --------------
__device__ float g_q[B_ * T_ * NH * HD];    // [bt][h][d]
__device__ float g_k[B_ * T_ * NKV * HD];   // [bt][kvh][d]
__device__ float g_v[B_ * T_ * NKV * HD];
__device__ float g_o[B_ * T_ * NH * HD];    // attention output

// ================= PTX helpers (baseline ISA only — no sm_103a features) =======
__device__ __forceinline__ uint32_t smem_u32(const void* p) {
    uint32_t a;
    asm("{ .reg .u64 t; cvta.to.shared.u64 t, %1; cvt.u32.u64 %0, t; }" : "=r"(a) : "l"(p));
    return a;
}
#define CP_ASYNC16(dst, src) \
    asm volatile("cp.async.cg.shared.global [%0], [%1], 16;" :: "r"(dst), "l"(src))
#define CP_COMMIT() asm volatile("cp.async.commit_group;" ::: "memory")
#define CP_WAIT(n)  asm volatile("cp.async.wait_group %0;" :: "n"(n) : "memory")

__device__ __forceinline__ uint32_t f2tf32(float f) {
    uint32_t u;
    asm("cvt.rna.tf32.f32 %0, %1;" : "=r"(u) : "f"(f));
    return u;
}
__device__ __forceinline__ void mma16n8k8(float* d, const uint32_t* a, const uint32_t* b) {
    asm volatile(
        "mma.sync.aligned.m16n8k8.row.col.f32.tf32.tf32.f32 "
        "{%0,%1,%2,%3}, {%4,%5,%6,%7}, {%8,%9}, {%0,%1,%2,%3};"
        : "+f"(d[0]), "+f"(d[1]), "+f"(d[2]), "+f"(d[3])
        : "r"(a[0]), "r"(a[1]), "r"(a[2]), "r"(a[3]), "r"(b[0]), "r"(b[1]));
}

// ================= tf32 mma.sync GEMM: C[M,N] = A[M,K] @ B[N,K]^T ==============
// 128x128x32 block tile, 256 threads (8 warps, 2x4), warp tile 64x32.
// smem: 2 stages x (As[128][36] + Bs[128][36]) floats, cp.async double buffer.
#define GK 32
#define G_PAD 36
#define G_STAGE_FLOATS (2 * 128 * G_PAD)
#define G_SMEM_BYTES (2 * G_STAGE_FLOATS * 4)

__global__ __launch_bounds__(256) void gemm_tf32(const float* __restrict__ A,
                                                 const float* __restrict__ Bm,
                                                 float* __restrict__ C,
                                                 int N, int K) {
    extern __shared__ float gsm[];
    const int tid = threadIdx.x;
    const int lane = tid & 31, wid = tid >> 5;
    const int wm = wid & 1, wn = wid >> 1;        // warp grid 2(m) x 4(n)
    const int m0 = wm * 64, n0 = wn * 32;
    const int bm = blockIdx.y * 128, bn = blockIdx.x * 128;

    const int lrow = tid >> 3;          // 0..31 -> covers 128 rows in 4 steps
    const int lc4 = (tid & 7) * 4;      // float4 col within 32-float chunk
    const uint32_t smem_base = smem_u32(gsm);

    const float* Ag = A + (size_t)(bm + lrow) * K + lc4;
    const float* Bg = Bm + (size_t)(bn + lrow) * K + lc4;

    float acc[4][4][4];
#pragma unroll
    for (int mt = 0; mt < 4; mt++)
#pragma unroll
        for (int nt = 0; nt < 4; nt++)
#pragma unroll
            for (int r = 0; r < 4; r++) acc[mt][nt][r] = 0.f;

    const int nch = K / GK;

    // ---- chunk loader: 128 rows x 32 floats for A and B into stage s ----------
    auto load_chunk = [&](int k, int s) {
        uint32_t sa = smem_base + (uint32_t)s * (G_STAGE_FLOATS * 4);
        uint32_t sb = sa + 128 * G_PAD * 4;
        const float* ag = Ag + (size_t)k * GK;
        const float* bg = Bg + (size_t)k * GK;
#pragma unroll
        for (int i = 0; i < 4; i++) {
            uint32_t off = (uint32_t)(lrow + i * 32) * (G_PAD * 4) + lc4 * 4;
            CP_ASYNC16(sa + off, ag + (size_t)(i * 32) * K);
            CP_ASYNC16(sb + off, bg + (size_t)(i * 32) * K);
        }
    };

    load_chunk(0, 0);
    CP_COMMIT();

    const int a_r = lane >> 2, a_c = lane & 3;

    for (int k = 0; k < nch; k++) {
        if (k + 1 < nch) {
            load_chunk(k + 1, (k + 1) & 1);
            CP_COMMIT();
            CP_WAIT(1);
        } else {
            CP_WAIT(0);
        }
        __syncthreads();

        const float* As = gsm + (k & 1) * G_STAGE_FLOATS;
        const float* Bs = As + 128 * G_PAD;

#pragma unroll
        for (int ks = 0; ks < 4; ks++) {
            uint32_t af[4][4], bf[4][2];
#pragma unroll
            for (int mt = 0; mt < 4; mt++) {
                const float* p = As + (m0 + mt * 16 + a_r) * G_PAD + ks * 8 + a_c;
                af[mt][0] = f2tf32(p[0]);
                af[mt][1] = f2tf32(p[8 * G_PAD]);
                af[mt][2] = f2tf32(p[4]);
                af[mt][3] = f2tf32(p[8 * G_PAD + 4]);
            }
#pragma unroll
            for (int nt = 0; nt < 4; nt++) {
                const float* p = Bs + (n0 + nt * 8 + a_r) * G_PAD + ks * 8 + a_c;
                bf[nt][0] = f2tf32(p[0]);
                bf[nt][1] = f2tf32(p[4]);
            }
#pragma unroll
            for (int mt = 0; mt < 4; mt++)
#pragma unroll
                for (int nt = 0; nt < 4; nt++)
                    mma16n8k8(acc[mt][nt], af[mt], bf[nt]);
        }
        __syncthreads();
    }

    // ---- epilogue: per-thread fragment rows (lane>>2, +8), cols 2*(lane&3) ----
#pragma unroll
    for (int mt = 0; mt < 4; mt++) {
        int r_lo = bm + m0 + mt * 16 + a_r;
#pragma unroll
        for (int nt = 0; nt < 4; nt++) {
            int col = bn + n0 + nt * 8 + 2 * a_c;
            *(float2*)(C + (size_t)r_lo * N + col) = make_float2(acc[mt][nt][0], acc[mt][nt][1]);
            *(float2*)(C + (size_t)(r_lo + 8) * N + col) = make_float2(acc[mt][nt][2], acc[mt][nt][3]);
        }
    }
}

// ---------------- RMSNorm + RoPE (one warp per head-vector of 96) --------------
__global__ void norm_rope_kernel(float* __restrict__ buf, const float* __restrict__ w,
                                 const float* __restrict__ cs, const float* __restrict__ sn,
                                 int nheads) {
    int warp = (blockIdx.x * blockDim.x + threadIdx.x) >> 5;
    int lane = threadIdx.x & 31;
    int total = B_ * T_ * nheads;
    if (warp >= total) return;
    int head = warp % nheads;
    int bt = warp / nheads;
    int t = bt % T_;
    float* v = buf + (size_t)(bt * nheads + head) * HD;

    float x0 = v[2 * lane], x1 = v[2 * lane + 1];
    float y0 = 0.f, y1 = 0.f;
    if (lane < 16) { y0 = v[64 + 2 * lane]; y1 = v[65 + 2 * lane]; }
    float ss = x0 * x0 + x1 * x1 + y0 * y0 + y1 * y1;
#pragma unroll
    for (int o = 16; o; o >>= 1) ss += __shfl_xor_sync(0xffffffffu, ss, o);
    float r = rsqrtf(ss / 96.f + 1e-6f);

    const float* cr = cs + t * HD;
    const float* sr = sn + t * HD;
    {
        int e0 = 2 * lane, e1 = e0 + 1;
        float a = x0 * w[e0] * r, b = x1 * w[e1] * r;
        v[e0] = a * cr[e0] - b * sr[e0];
        v[e1] = a * sr[e1] + b * cr[e1];
    }
    if (lane < 16) {
        int e0 = 64 + 2 * lane, e1 = e0 + 1;
        float a = y0 * w[e0] * r, b = y1 * w[e1] * r;
        v[e0] = a * cr[e0] - b * sr[e0];
        v[e1] = a * sr[e1] + b * cr[e1];
    }
}

// ---------------- Flash attention (fp32, Br=Bc=64, online softmax) -------------
#define QK_STR 68    // Qs/Ks stored d-major: [96][64+pad]
#define V_STR 100    // Vs row-major: [64][96+pad]
#define P_STR 68     // Ps stored k-major: [64][64+pad]

__global__ __launch_bounds__(256) void flash_kernel(const float* __restrict__ Q,
                                                    const float* __restrict__ K,
                                                    const float* __restrict__ V,
                                                    float* __restrict__ O) {
    extern __shared__ float sm[];
    float* Qs = sm;                       // 96*68
    float* Ks = Qs + 96 * QK_STR;         // 96*68
    float* Vs = Ks + 96 * QK_STR;         // 64*100
    float* Ps = Vs + 64 * V_STR;          // 64*68  (k-major: Ps[k][row])

    int qt = blockIdx.x;                  // 0..15
    int bh = blockIdx.y;                  // b*32 + h
    int b = bh >> 5, h = bh & 31;
    int kvh = h >> 2;

    int tid = threadIdx.x;
    int tx = tid & 15, ty = tid >> 4;
    const float scale = 0.10206207261596575f;  // 1/sqrt(96)

    const float* Qg = Q + ((size_t)(b * T_ + qt * 64) * NH + h) * HD;
    const float* Kg = K + (size_t)b * T_ * NKV * HD + kvh * HD;
    const float* Vg = V + (size_t)b * T_ * NKV * HD + kvh * HD;

    for (int i = tid; i < 64 * 24; i += 256) {
        int rrow = i / 24, c4 = (i % 24) * 4;
        float4 vq = *(const float4*)(Qg + (size_t)rrow * (NH * HD) + c4);
        Qs[(c4 + 0) * QK_STR + rrow] = vq.x * scale;
        Qs[(c4 + 1) * QK_STR + rrow] = vq.y * scale;
        Qs[(c4 + 2) * QK_STR + rrow] = vq.z * scale;
        Qs[(c4 + 3) * QK_STR + rrow] = vq.w * scale;
    }

    float mrow[4], lrow[4], oacc[4][6];
#pragma unroll
    for (int i = 0; i < 4; i++) {
        mrow[i] = -INFINITY; lrow[i] = 0.f;
#pragma unroll
        for (int j = 0; j < 6; j++) oacc[i][j] = 0.f;
    }
    int q_row0 = qt * 64;

    for (int jt = 0; jt <= qt; jt++) {
        __syncthreads();
        for (int i = tid; i < 64 * 24; i += 256) {
            int rrow = i / 24, c4 = (i % 24) * 4;
            float4 vk = *(const float4*)(Kg + (size_t)(jt * 64 + rrow) * (NKV * HD) + c4);
            Ks[(c4 + 0) * QK_STR + rrow] = vk.x;
            Ks[(c4 + 1) * QK_STR + rrow] = vk.y;
            Ks[(c4 + 2) * QK_STR + rrow] = vk.z;
            Ks[(c4 + 3) * QK_STR + rrow] = vk.w;
            float4 vv = *(const float4*)(Vg + (size_t)(jt * 64 + rrow) * (NKV * HD) + c4);
            *(float4*)(Vs + rrow * V_STR + c4) = vv;
        }
        __syncthreads();

        float s[4][4];
#pragma unroll
        for (int i = 0; i < 4; i++)
#pragma unroll
            for (int j = 0; j < 4; j++) s[i][j] = 0.f;
#pragma unroll 8
        for (int d = 0; d < 96; d++) {
            float4 aq = *(const float4*)(Qs + d * QK_STR + ty * 4);
            float4 bk = *(const float4*)(Ks + d * QK_STR + tx * 4);
            float ar[4] = {aq.x, aq.y, aq.z, aq.w};
            float br[4] = {bk.x, bk.y, bk.z, bk.w};
#pragma unroll
            for (int i = 0; i < 4; i++)
#pragma unroll
                for (int j = 0; j < 4; j++) s[i][j] = fmaf(ar[i], br[j], s[i][j]);
        }

        if (jt == qt) {
#pragma unroll
            for (int i = 0; i < 4; i++)
#pragma unroll
                for (int j = 0; j < 4; j++)
                    if (jt * 64 + tx * 4 + j > q_row0 + ty * 4 + i) s[i][j] = -INFINITY;
        }

#pragma unroll
        for (int i = 0; i < 4; i++) {
            float tm = fmaxf(fmaxf(s[i][0], s[i][1]), fmaxf(s[i][2], s[i][3]));
#pragma unroll
            for (int o = 8; o; o >>= 1) tm = fmaxf(tm, __shfl_xor_sync(0xffffffffu, tm, o));
            float nm = fmaxf(mrow[i], tm);
            float alpha = __expf(mrow[i] - nm);
            mrow[i] = nm;
            float rs = 0.f;
#pragma unroll
            for (int j = 0; j < 4; j++) { s[i][j] = __expf(s[i][j] - nm); rs += s[i][j]; }
#pragma unroll
            for (int o = 8; o; o >>= 1) rs += __shfl_xor_sync(0xffffffffu, rs, o);
            lrow[i] = lrow[i] * alpha + rs;
#pragma unroll
            for (int j = 0; j < 6; j++) oacc[i][j] *= alpha;
#pragma unroll
            for (int j = 0; j < 4; j++)
                Ps[(tx * 4 + j) * P_STR + ty * 4 + i] = s[i][j];
        }
        __syncthreads();

#pragma unroll 4
        for (int k = 0; k < 64; k++) {
            float4 p = *(const float4*)(Ps + k * P_STR + ty * 4);
            float2 v0 = *(const float2*)(Vs + k * V_STR + tx * 6);
            float2 v1 = *(const float2*)(Vs + k * V_STR + tx * 6 + 2);
            float2 v2 = *(const float2*)(Vs + k * V_STR + tx * 6 + 4);
            float pv[4] = {p.x, p.y, p.z, p.w};
            float vv[6] = {v0.x, v0.y, v1.x, v1.y, v2.x, v2.y};
#pragma unroll
            for (int i = 0; i < 4; i++)
#pragma unroll
                for (int j = 0; j < 6; j++) oacc[i][j] = fmaf(pv[i], vv[j], oacc[i][j]);
        }
    }

#pragma unroll
    for (int i = 0; i < 4; i++) {
        float inv = 1.f / lrow[i];
        float* Og = O + ((size_t)(b * T_ + q_row0 + ty * 4 + i) * NH + h) * HD + tx * 6;
        float2 w0 = make_float2(oacc[i][0] * inv, oacc[i][1] * inv);
        float2 w1 = make_float2(oacc[i][2] * inv, oacc[i][3] * inv);
        float2 w2 = make_float2(oacc[i][4] * inv, oacc[i][5] * inv);
        *(float2*)(Og + 0) = w0;
        *(float2*)(Og + 2) = w1;
        *(float2*)(Og + 4) = w2;
    }
}

// ---------------- launch -------------------------------------------------------
extern "C" void kernel_launch(void* const* d_in, const int* in_sizes, int n_in,
                              void* d_out, int out_size) {
    const float* x   = (const float*)d_in[0];
    const float* wq  = (const float*)d_in[2];
    const float* wk  = (const float*)d_in[3];
    const float* wv  = (const float*)d_in[4];
    const float* wo  = (const float*)d_in[5];
    const float* qnw = (const float*)d_in[6];
    const float* knw = (const float*)d_in[7];
    const float* cs  = (const float*)d_in[8];
    const float* sn  = (const float*)d_in[9];
    float* out = (float*)d_out;

    float *q_buf, *k_buf, *v_buf, *o_buf;
    cudaGetSymbolAddress((void**)&q_buf, g_q);
    cudaGetSymbolAddress((void**)&k_buf, g_k);
    cudaGetSymbolAddress((void**)&v_buf, g_v);
    cudaGetSymbolAddress((void**)&o_buf, g_o);

    const int M = B_ * T_;  // 2048

    cudaFuncSetAttribute(gemm_tf32, cudaFuncAttributeMaxDynamicSharedMemorySize, G_SMEM_BYTES);

    // QKV projections (tf32 mma.sync)
    dim3 gq(DM / 128, M / 128);
    gemm_tf32<<<gq, 256, G_SMEM_BYTES>>>(x, wq, q_buf, DM, DM);
    dim3 gkv((NKV * HD) / 128, M / 128);
    gemm_tf32<<<gkv, 256, G_SMEM_BYTES>>>(x, wk, k_buf, NKV * HD, DM);
    gemm_tf32<<<gkv, 256, G_SMEM_BYTES>>>(x, wv, v_buf, NKV * HD, DM);

    // RMSNorm + RoPE
    {
        int warps_q = M * NH;
        norm_rope_kernel<<<(warps_q * 32 + 255) / 256, 256>>>(q_buf, qnw, cs, sn, NH);
        int warps_k = M * NKV;
        norm_rope_kernel<<<(warps_k * 32 + 255) / 256, 256>>>(k_buf, knw, cs, sn, NKV);
    }

    // Flash attention (fp32)
    {
        size_t smem = (size_t)(96 * QK_STR * 2 + 64 * V_STR + 64 * P_STR) * sizeof(float);
        cudaFuncSetAttribute(flash_kernel, cudaFuncAttributeMaxDynamicSharedMemorySize, (int)smem);
        dim3 grid(T_ / 64, B_ * NH);
        flash_kernel<<<grid, 256, smem>>>(q_buf, k_buf, v_buf, o_buf);
    }

    // output projection (tf32 mma.sync)
    gemm_tf32<<<gq, 256, G_SMEM_BYTES>>>(o_buf, wo, out, DM, DM);
}

// round 13
// speedup vs baseline: 2.6146x; 1.7029x over previous
#include <cuda_runtime.h>
#include <cuda_bf16.h>
#include <math.h>
#include <cstdint>

#define B_ 2
#define T_ 1024
#define DM 3072
#define NH 32
#define NKV 8
#define HD 96

// ---------------- scratch (device globals; no allocation allowed) --------------
__device__ float g_q[B_ * T_ * NH * HD];    // [bt][h][d]
__device__ float g_k[B_ * T_ * NKV * HD];   // [bt][kvh][d]
__device__ float g_v[B_ * T_ * NKV * HD];
__device__ float g_o[B_ * T_ * NH * HD];    // attention output

// ================= PTX helpers (baseline ISA only — no sm_103a features) =======
__device__ __forceinline__ uint32_t smem_u32(const void* p) {
    uint32_t a;
    asm("{ .reg .u64 t; cvta.to.shared.u64 t, %1; cvt.u32.u64 %0, t; }" : "=r"(a) : "l"(p));
    return a;
}
#define CP_ASYNC16(dst, src) \
    asm volatile("cp.async.cg.shared.global [%0], [%1], 16;" :: "r"(dst), "l"(src))
#define CP_COMMIT() asm volatile("cp.async.commit_group;" ::: "memory")
#define CP_WAIT(n)  asm volatile("cp.async.wait_group %0;" :: "n"(n) : "memory")

__device__ __forceinline__ uint32_t f2tf32(float f) {
    uint32_t u;
    asm("cvt.rna.tf32.f32 %0, %1;" : "=r"(u) : "f"(f));
    return u;
}
__device__ __forceinline__ void mma16n8k8(float* d, const uint32_t* a, const uint32_t* b) {
    asm volatile(
        "mma.sync.aligned.m16n8k8.row.col.f32.tf32.tf32.f32 "
        "{%0,%1,%2,%3}, {%4,%5,%6,%7}, {%8,%9}, {%0,%1,%2,%3};"
        : "+f"(d[0]), "+f"(d[1]), "+f"(d[2]), "+f"(d[3])
        : "r"(a[0]), "r"(a[1]), "r"(a[2]), "r"(a[3]), "r"(b[0]), "r"(b[1]));
}

// ================= tf32 mma.sync GEMM core: C[.,N] tile = A tile @ B tile^T ====
// 128x128x32 block tile, 256 threads (8 warps, 2x4), warp tile 64x32.
// smem: 2 stages x (As[128][36] + Bs[128][36]) floats, cp.async double buffer.
#define GK 32
#define G_PAD 36
#define G_STAGE_FLOATS (2 * 128 * G_PAD)
#define G_SMEM_BYTES (2 * G_STAGE_FLOATS * 4)

__device__ __forceinline__ void gemm_core(const float* __restrict__ A,
                                          const float* __restrict__ Bm,
                                          float* __restrict__ C,
                                          int N, int K, int bm, int bn,
                                          float* gsm) {
    const int tid = threadIdx.x;
    const int lane = tid & 31, wid = tid >> 5;
    const int wm = wid & 1, wn = wid >> 1;        // warp grid 2(m) x 4(n)
    const int m0 = wm * 64, n0 = wn * 32;

    const int lrow = tid >> 3;          // 0..31 -> covers 128 rows in 4 steps
    const int lc4 = (tid & 7) * 4;      // float4 col within 32-float chunk
    const uint32_t smem_base = smem_u32(gsm);

    const float* Ag = A + (size_t)(bm + lrow) * K + lc4;
    const float* Bg = Bm + (size_t)(bn + lrow) * K + lc4;

    float acc[4][4][4];
#pragma unroll
    for (int mt = 0; mt < 4; mt++)
#pragma unroll
        for (int nt = 0; nt < 4; nt++)
#pragma unroll
            for (int r = 0; r < 4; r++) acc[mt][nt][r] = 0.f;

    const int nch = K / GK;

    auto load_chunk = [&](int k, int s) {
        uint32_t sa = smem_base + (uint32_t)s * (G_STAGE_FLOATS * 4);
        uint32_t sb = sa + 128 * G_PAD * 4;
        const float* ag = Ag + (size_t)k * GK;
        const float* bg = Bg + (size_t)k * GK;
#pragma unroll
        for (int i = 0; i < 4; i++) {
            uint32_t off = (uint32_t)(lrow + i * 32) * (G_PAD * 4) + lc4 * 4;
            CP_ASYNC16(sa + off, ag + (size_t)(i * 32) * K);
            CP_ASYNC16(sb + off, bg + (size_t)(i * 32) * K);
        }
    };

    load_chunk(0, 0);
    CP_COMMIT();

    const int a_r = lane >> 2, a_c = lane & 3;

    for (int k = 0; k < nch; k++) {
        if (k + 1 < nch) {
            load_chunk(k + 1, (k + 1) & 1);
            CP_COMMIT();
            CP_WAIT(1);
        } else {
            CP_WAIT(0);
        }
        __syncthreads();

        const float* As = gsm + (k & 1) * G_STAGE_FLOATS;
        const float* Bs = As + 128 * G_PAD;

#pragma unroll
        for (int ks = 0; ks < 4; ks++) {
            uint32_t af[4][4], bf[4][2];
#pragma unroll
            for (int mt = 0; mt < 4; mt++) {
                const float* p = As + (m0 + mt * 16 + a_r) * G_PAD + ks * 8 + a_c;
                af[mt][0] = f2tf32(p[0]);
                af[mt][1] = f2tf32(p[8 * G_PAD]);
                af[mt][2] = f2tf32(p[4]);
                af[mt][3] = f2tf32(p[8 * G_PAD + 4]);
            }
#pragma unroll
            for (int nt = 0; nt < 4; nt++) {
                const float* p = Bs + (n0 + nt * 8 + a_r) * G_PAD + ks * 8 + a_c;
                bf[nt][0] = f2tf32(p[0]);
                bf[nt][1] = f2tf32(p[4]);
            }
#pragma unroll
            for (int mt = 0; mt < 4; mt++)
#pragma unroll
                for (int nt = 0; nt < 4; nt++)
                    mma16n8k8(acc[mt][nt], af[mt], bf[nt]);
        }
        __syncthreads();
    }

    // epilogue: per-thread fragment rows (lane>>2, +8), cols 2*(lane&3)
#pragma unroll
    for (int mt = 0; mt < 4; mt++) {
        int r_lo = bm + m0 + mt * 16 + a_r;
#pragma unroll
        for (int nt = 0; nt < 4; nt++) {
            int col = bn + n0 + nt * 8 + 2 * a_c;
            *(float2*)(C + (size_t)r_lo * N + col) = make_float2(acc[mt][nt][0], acc[mt][nt][1]);
            *(float2*)(C + (size_t)(r_lo + 8) * N + col) = make_float2(acc[mt][nt][2], acc[mt][nt][3]);
        }
    }
}

// generic GEMM (used for output projection): C[M,N] = A[M,K] @ B[N,K]^T
__global__ __launch_bounds__(256) void gemm_tf32(const float* __restrict__ A,
                                                 const float* __restrict__ Bm,
                                                 float* __restrict__ C,
                                                 int N, int K) {
    extern __shared__ float gsm[];
    gemm_core(A, Bm, C, N, K, blockIdx.y * 128, blockIdx.x * 128, gsm);
}

// fused QKV projection: one grid over N_total = 3072 + 768 + 768 = 4608.
// Block N-ranges route wholly to one (weight, output) pair since boundaries
// (3072, 3840) are multiples of the 128-wide N tile.
__global__ __launch_bounds__(256) void gemm_qkv(const float* __restrict__ x,
                                                const float* __restrict__ wq,
                                                const float* __restrict__ wk,
                                                const float* __restrict__ wv,
                                                float* __restrict__ qb,
                                                float* __restrict__ kb,
                                                float* __restrict__ vb) {
    extern __shared__ float gsm[];
    int bn = blockIdx.x * 128;
    const float* Bsrc;
    float* Cdst;
    int Nc, bnl;
    if (bn < 3072)      { Bsrc = wq; Cdst = qb; Nc = 3072; bnl = bn; }
    else if (bn < 3840) { Bsrc = wk; Cdst = kb; Nc = 768;  bnl = bn - 3072; }
    else                { Bsrc = wv; Cdst = vb; Nc = 768;  bnl = bn - 3840; }
    gemm_core(x, Bsrc, Cdst, Nc, DM, blockIdx.y * 128, bnl, gsm);
}

// ---------------- RMSNorm + RoPE (one warp per head-vector of 96) --------------
__global__ void norm_rope_kernel(float* __restrict__ buf, const float* __restrict__ w,
                                 const float* __restrict__ cs, const float* __restrict__ sn,
                                 int nheads) {
    int warp = (blockIdx.x * blockDim.x + threadIdx.x) >> 5;
    int lane = threadIdx.x & 31;
    int total = B_ * T_ * nheads;
    if (warp >= total) return;
    int head = warp % nheads;
    int bt = warp / nheads;
    int t = bt % T_;
    float* v = buf + (size_t)(bt * nheads + head) * HD;

    float x0 = v[2 * lane], x1 = v[2 * lane + 1];
    float y0 = 0.f, y1 = 0.f;
    if (lane < 16) { y0 = v[64 + 2 * lane]; y1 = v[65 + 2 * lane]; }
    float ss = x0 * x0 + x1 * x1 + y0 * y0 + y1 * y1;
#pragma unroll
    for (int o = 16; o; o >>= 1) ss += __shfl_xor_sync(0xffffffffu, ss, o);
    float r = rsqrtf(ss / 96.f + 1e-6f);

    const float* cr = cs + t * HD;
    const float* sr = sn + t * HD;
    {
        int e0 = 2 * lane, e1 = e0 + 1;
        float a = x0 * w[e0] * r, b = x1 * w[e1] * r;
        v[e0] = a * cr[e0] - b * sr[e0];
        v[e1] = a * sr[e1] + b * cr[e1];
    }
    if (lane < 16) {
        int e0 = 64 + 2 * lane, e1 = e0 + 1;
        float a = y0 * w[e0] * r, b = y1 * w[e1] * r;
        v[e0] = a * cr[e0] - b * sr[e0];
        v[e1] = a * sr[e1] + b * cr[e1];
    }
}

// ---------------- Flash attention (fp32, Br=Bc=64, online softmax) -------------
#define QK_STR 68    // Qs/Ks stored d-major: [96][64+pad]
#define V_STR 100    // Vs row-major: [64][96+pad]
#define P_STR 68     // Ps stored k-major: [64][64+pad]

__global__ __launch_bounds__(256) void flash_kernel(const float* __restrict__ Q,
                                                    const float* __restrict__ K,
                                                    const float* __restrict__ V,
                                                    float* __restrict__ O) {
    extern __shared__ float sm[];
    float* Qs = sm;                       // 96*68
    float* Ks = Qs + 96 * QK_STR;         // 96*68
    float* Vs = Ks + 96 * QK_STR;         // 64*100
    float* Ps = Vs + 64 * V_STR;          // 64*68  (k-major: Ps[k][row])

    int qt = blockIdx.x;                  // 0..15
    int bh = blockIdx.y;                  // b*32 + h
    int b = bh >> 5, h = bh & 31;
    int kvh = h >> 2;

    int tid = threadIdx.x;
    int tx = tid & 15, ty = tid >> 4;
    const float scale = 0.10206207261596575f;  // 1/sqrt(96)

    const float* Qg = Q + ((size_t)(b * T_ + qt * 64) * NH + h) * HD;
    const float* Kg = K + (size_t)b * T_ * NKV * HD + kvh * HD;
    const float* Vg = V + (size_t)b * T_ * NKV * HD + kvh * HD;

    for (int i = tid; i < 64 * 24; i += 256) {
        int rrow = i / 24, c4 = (i % 24) * 4;
        float4 vq = *(const float4*)(Qg + (size_t)rrow * (NH * HD) + c4);
        Qs[(c4 + 0) * QK_STR + rrow] = vq.x * scale;
        Qs[(c4 + 1) * QK_STR + rrow] = vq.y * scale;
        Qs[(c4 + 2) * QK_STR + rrow] = vq.z * scale;
        Qs[(c4 + 3) * QK_STR + rrow] = vq.w * scale;
    }

    float mrow[4], lrow[4], oacc[4][6];
#pragma unroll
    for (int i = 0; i < 4; i++) {
        mrow[i] = -INFINITY; lrow[i] = 0.f;
#pragma unroll
        for (int j = 0; j < 6; j++) oacc[i][j] = 0.f;
    }
    int q_row0 = qt * 64;

    for (int jt = 0; jt <= qt; jt++) {
        __syncthreads();
        for (int i = tid; i < 64 * 24; i += 256) {
            int rrow = i / 24, c4 = (i % 24) * 4;
            float4 vk = *(const float4*)(Kg + (size_t)(jt * 64 + rrow) * (NKV * HD) + c4);
            Ks[(c4 + 0) * QK_STR + rrow] = vk.x;
            Ks[(c4 + 1) * QK_STR + rrow] = vk.y;
            Ks[(c4 + 2) * QK_STR + rrow] = vk.z;
            Ks[(c4 + 3) * QK_STR + rrow] = vk.w;
            float4 vv = *(const float4*)(Vg + (size_t)(jt * 64 + rrow) * (NKV * HD) + c4);
            *(float4*)(Vs + rrow * V_STR + c4) = vv;
        }
        __syncthreads();

        float s[4][4];
#pragma unroll
        for (int i = 0; i < 4; i++)
#pragma unroll
            for (int j = 0; j < 4; j++) s[i][j] = 0.f;
#pragma unroll 8
        for (int d = 0; d < 96; d++) {
            float4 aq = *(const float4*)(Qs + d * QK_STR + ty * 4);
            float4 bk = *(const float4*)(Ks + d * QK_STR + tx * 4);
            float ar[4] = {aq.x, aq.y, aq.z, aq.w};
            float br[4] = {bk.x, bk.y, bk.z, bk.w};
#pragma unroll
            for (int i = 0; i < 4; i++)
#pragma unroll
                for (int j = 0; j < 4; j++) s[i][j] = fmaf(ar[i], br[j], s[i][j]);
        }

        if (jt == qt) {
#pragma unroll
            for (int i = 0; i < 4; i++)
#pragma unroll
                for (int j = 0; j < 4; j++)
                    if (jt * 64 + tx * 4 + j > q_row0 + ty * 4 + i) s[i][j] = -INFINITY;
        }

#pragma unroll
        for (int i = 0; i < 4; i++) {
            float tm = fmaxf(fmaxf(s[i][0], s[i][1]), fmaxf(s[i][2], s[i][3]));
#pragma unroll
            for (int o = 8; o; o >>= 1) tm = fmaxf(tm, __shfl_xor_sync(0xffffffffu, tm, o));
            float nm = fmaxf(mrow[i], tm);
            float alpha = __expf(mrow[i] - nm);
            mrow[i] = nm;
            float rs = 0.f;
#pragma unroll
            for (int j = 0; j < 4; j++) { s[i][j] = __expf(s[i][j] - nm); rs += s[i][j]; }
#pragma unroll
            for (int o = 8; o; o >>= 1) rs += __shfl_xor_sync(0xffffffffu, rs, o);
            lrow[i] = lrow[i] * alpha + rs;
#pragma unroll
            for (int j = 0; j < 6; j++) oacc[i][j] *= alpha;
#pragma unroll
            for (int j = 0; j < 4; j++)
                Ps[(tx * 4 + j) * P_STR + ty * 4 + i] = s[i][j];
        }
        __syncthreads();

#pragma unroll 4
        for (int k = 0; k < 64; k++) {
            float4 p = *(const float4*)(Ps + k * P_STR + ty * 4);
            float2 v0 = *(const float2*)(Vs + k * V_STR + tx * 6);
            float2 v1 = *(const float2*)(Vs + k * V_STR + tx * 6 + 2);
            float2 v2 = *(const float2*)(Vs + k * V_STR + tx * 6 + 4);
            float pv[4] = {p.x, p.y, p.z, p.w};
            float vv[6] = {v0.x, v0.y, v1.x, v1.y, v2.x, v2.y};
#pragma unroll
            for (int i = 0; i < 4; i++)
#pragma unroll
                for (int j = 0; j < 6; j++) oacc[i][j] = fmaf(pv[i], vv[j], oacc[i][j]);
        }
    }

#pragma unroll
    for (int i = 0; i < 4; i++) {
        float inv = 1.f / lrow[i];
        float* Og = O + ((size_t)(b * T_ + q_row0 + ty * 4 + i) * NH + h) * HD + tx * 6;
        float2 w0 = make_float2(oacc[i][0] * inv, oacc[i][1] * inv);
        float2 w1 = make_float2(oacc[i][2] * inv, oacc[i][3] * inv);
        float2 w2 = make_float2(oacc[i][4] * inv, oacc[i][5] * inv);
        *(float2*)(Og + 0) = w0;
        *(float2*)(Og + 2) = w1;
        *(float2*)(Og + 4) = w2;
    }
}

// ---------------- launch -------------------------------------------------------
extern "C" void kernel_launch(void* const* d_in, const int* in_sizes, int n_in,
                              void* d_out, int out_size) {
    const float* x   = (const float*)d_in[0];
    const float* wq  = (const float*)d_in[2];
    const float* wk  = (const float*)d_in[3];
    const float* wv  = (const float*)d_in[4];
    const float* wo  = (const float*)d_in[5];
    const float* qnw = (const float*)d_in[6];
    const float* knw = (const float*)d_in[7];
    const float* cs  = (const float*)d_in[8];
    const float* sn  = (const float*)d_in[9];
    float* out = (float*)d_out;

    float *q_buf, *k_buf, *v_buf, *o_buf;
    cudaGetSymbolAddress((void**)&q_buf, g_q);
    cudaGetSymbolAddress((void**)&k_buf, g_k);
    cudaGetSymbolAddress((void**)&v_buf, g_v);
    cudaGetSymbolAddress((void**)&o_buf, g_o);

    const int M = B_ * T_;  // 2048

    cudaFuncSetAttribute(gemm_qkv, cudaFuncAttributeMaxDynamicSharedMemorySize, G_SMEM_BYTES);
    cudaFuncSetAttribute(gemm_tf32, cudaFuncAttributeMaxDynamicSharedMemorySize, G_SMEM_BYTES);

    // fused QKV projection: N_total = 4608 -> 36 x 16 = 576 blocks (~1.95 waves)
    {
        dim3 g((DM + 2 * NKV * HD) / 128, M / 128);
        gemm_qkv<<<g, 256, G_SMEM_BYTES>>>(x, wq, wk, wv, q_buf, k_buf, v_buf);
    }

    // RMSNorm + RoPE
    {
        int warps_q = M * NH;
        norm_rope_kernel<<<(warps_q * 32 + 255) / 256, 256>>>(q_buf, qnw, cs, sn, NH);
        int warps_k = M * NKV;
        norm_rope_kernel<<<(warps_k * 32 + 255) / 256, 256>>>(k_buf, knw, cs, sn, NKV);
    }

    // Flash attention (fp32)
    {
        size_t smem = (size_t)(96 * QK_STR * 2 + 64 * V_STR + 64 * P_STR) * sizeof(float);
        cudaFuncSetAttribute(flash_kernel, cudaFuncAttributeMaxDynamicSharedMemorySize, (int)smem);
        dim3 grid(T_ / 64, B_ * NH);
        flash_kernel<<<grid, 256, smem>>>(q_buf, k_buf, v_buf, o_buf);
    }

    // output projection (tf32 mma.sync)
    dim3 go(DM / 128, M / 128);
    gemm_tf32<<<go, 256, G_SMEM_BYTES>>>(o_buf, wo, out, DM, DM);
}

// round 14
// speedup vs baseline: 3.3214x; 1.2703x over previous
#include <cuda_runtime.h>
#include <cuda_bf16.h>
#include <math.h>
#include <cstdint>

#define B_ 2
#define T_ 1024
#define DM 3072
#define NH 32
#define NKV 8
#define HD 96

// ---------------- scratch (device globals; no allocation allowed) --------------
__device__ float g_q[B_ * T_ * NH * HD];    // [bt][h][d]
__device__ float g_k[B_ * T_ * NKV * HD];   // [bt][kvh][d]
__device__ float g_v[B_ * T_ * NKV * HD];
__device__ float g_o[B_ * T_ * NH * HD];    // attention output

// ================= PTX helpers (baseline ISA only — no sm_103a features) =======
__device__ __forceinline__ uint32_t smem_u32(const void* p) {
    uint32_t a;
    asm("{ .reg .u64 t; cvta.to.shared.u64 t, %1; cvt.u32.u64 %0, t; }" : "=r"(a) : "l"(p));
    return a;
}
#define CP_ASYNC16(dst, src) \
    asm volatile("cp.async.cg.shared.global [%0], [%1], 16;" :: "r"(dst), "l"(src))
#define CP_COMMIT() asm volatile("cp.async.commit_group;" ::: "memory")
#define CP_WAIT(n)  asm volatile("cp.async.wait_group %0;" :: "n"(n) : "memory")

__device__ __forceinline__ uint32_t f2tf32(float f) {
    uint32_t u;
    asm("cvt.rna.tf32.f32 %0, %1;" : "=r"(u) : "f"(f));
    return u;
}
__device__ __forceinline__ void mma16n8k8(float* d, const uint32_t* a, const uint32_t* b) {
    asm volatile(
        "mma.sync.aligned.m16n8k8.row.col.f32.tf32.tf32.f32 "
        "{%0,%1,%2,%3}, {%4,%5,%6,%7}, {%8,%9}, {%0,%1,%2,%3};"
        : "+f"(d[0]), "+f"(d[1]), "+f"(d[2]), "+f"(d[3])
        : "r"(a[0]), "r"(a[1]), "r"(a[2]), "r"(a[3]), "r"(b[0]), "r"(b[1]));
}

// ================= tf32 mma.sync GEMM core: C[.,N] tile = A tile @ B tile^T ====
#define GK 32
#define G_PAD 36
#define G_STAGE_FLOATS (2 * 128 * G_PAD)
#define G_SMEM_BYTES (2 * G_STAGE_FLOATS * 4)

__device__ __forceinline__ void gemm_core(const float* __restrict__ A,
                                          const float* __restrict__ Bm,
                                          float* __restrict__ C,
                                          int N, int K, int bm, int bn,
                                          float* gsm) {
    const int tid = threadIdx.x;
    const int lane = tid & 31, wid = tid >> 5;
    const int wm = wid & 1, wn = wid >> 1;        // warp grid 2(m) x 4(n)
    const int m0 = wm * 64, n0 = wn * 32;

    const int lrow = tid >> 3;
    const int lc4 = (tid & 7) * 4;
    const uint32_t smem_base = smem_u32(gsm);

    const float* Ag = A + (size_t)(bm + lrow) * K + lc4;
    const float* Bg = Bm + (size_t)(bn + lrow) * K + lc4;

    float acc[4][4][4];
#pragma unroll
    for (int mt = 0; mt < 4; mt++)
#pragma unroll
        for (int nt = 0; nt < 4; nt++)
#pragma unroll
            for (int r = 0; r < 4; r++) acc[mt][nt][r] = 0.f;

    const int nch = K / GK;

    auto load_chunk = [&](int k, int s) {
        uint32_t sa = smem_base + (uint32_t)s * (G_STAGE_FLOATS * 4);
        uint32_t sb = sa + 128 * G_PAD * 4;
        const float* ag = Ag + (size_t)k * GK;
        const float* bg = Bg + (size_t)k * GK;
#pragma unroll
        for (int i = 0; i < 4; i++) {
            uint32_t off = (uint32_t)(lrow + i * 32) * (G_PAD * 4) + lc4 * 4;
            CP_ASYNC16(sa + off, ag + (size_t)(i * 32) * K);
            CP_ASYNC16(sb + off, bg + (size_t)(i * 32) * K);
        }
    };

    load_chunk(0, 0);
    CP_COMMIT();

    const int a_r = lane >> 2, a_c = lane & 3;

    for (int k = 0; k < nch; k++) {
        if (k + 1 < nch) {
            load_chunk(k + 1, (k + 1) & 1);
            CP_COMMIT();
            CP_WAIT(1);
        } else {
            CP_WAIT(0);
        }
        __syncthreads();

        const float* As = gsm + (k & 1) * G_STAGE_FLOATS;
        const float* Bs = As + 128 * G_PAD;

#pragma unroll
        for (int ks = 0; ks < 4; ks++) {
            uint32_t af[4][4], bf[4][2];
#pragma unroll
            for (int mt = 0; mt < 4; mt++) {
                const float* p = As + (m0 + mt * 16 + a_r) * G_PAD + ks * 8 + a_c;
                af[mt][0] = f2tf32(p[0]);
                af[mt][1] = f2tf32(p[8 * G_PAD]);
                af[mt][2] = f2tf32(p[4]);
                af[mt][3] = f2tf32(p[8 * G_PAD + 4]);
            }
#pragma unroll
            for (int nt = 0; nt < 4; nt++) {
                const float* p = Bs + (n0 + nt * 8 + a_r) * G_PAD + ks * 8 + a_c;
                bf[nt][0] = f2tf32(p[0]);
                bf[nt][1] = f2tf32(p[4]);
            }
#pragma unroll
            for (int mt = 0; mt < 4; mt++)
#pragma unroll
                for (int nt = 0; nt < 4; nt++)
                    mma16n8k8(acc[mt][nt], af[mt], bf[nt]);
        }
        __syncthreads();
    }

#pragma unroll
    for (int mt = 0; mt < 4; mt++) {
        int r_lo = bm + m0 + mt * 16 + a_r;
#pragma unroll
        for (int nt = 0; nt < 4; nt++) {
            int col = bn + n0 + nt * 8 + 2 * a_c;
            *(float2*)(C + (size_t)r_lo * N + col) = make_float2(acc[mt][nt][0], acc[mt][nt][1]);
            *(float2*)(C + (size_t)(r_lo + 8) * N + col) = make_float2(acc[mt][nt][2], acc[mt][nt][3]);
        }
    }
}

__global__ __launch_bounds__(256) void gemm_tf32(const float* __restrict__ A,
                                                 const float* __restrict__ Bm,
                                                 float* __restrict__ C,
                                                 int N, int K) {
    extern __shared__ float gsm[];
    gemm_core(A, Bm, C, N, K, blockIdx.y * 128, blockIdx.x * 128, gsm);
}

// fused QKV projection over N_total = 3072+768+768 = 4608
__global__ __launch_bounds__(256) void gemm_qkv(const float* __restrict__ x,
                                                const float* __restrict__ wq,
                                                const float* __restrict__ wk,
                                                const float* __restrict__ wv,
                                                float* __restrict__ qb,
                                                float* __restrict__ kb,
                                                float* __restrict__ vb) {
    extern __shared__ float gsm[];
    int bn = blockIdx.x * 128;
    const float* Bsrc;
    float* Cdst;
    int Nc, bnl;
    if (bn < 3072)      { Bsrc = wq; Cdst = qb; Nc = 3072; bnl = bn; }
    else if (bn < 3840) { Bsrc = wk; Cdst = kb; Nc = 768;  bnl = bn - 3072; }
    else                { Bsrc = wv; Cdst = vb; Nc = 768;  bnl = bn - 3840; }
    gemm_core(x, Bsrc, Cdst, Nc, DM, blockIdx.y * 128, bnl, gsm);
}

// ---------------- fused RMSNorm + RoPE (one warp per head-vector) --------------
__global__ void norm_rope_fused(float* __restrict__ qb, float* __restrict__ kb,
                                const float* __restrict__ qw, const float* __restrict__ kw,
                                const float* __restrict__ cs, const float* __restrict__ sn) {
    int warp = (blockIdx.x * blockDim.x + threadIdx.x) >> 5;
    int lane = threadIdx.x & 31;
    const int qtot = B_ * T_ * NH;
    const int ktot = B_ * T_ * NKV;
    if (warp >= qtot + ktot) return;
    float* v;
    const float* w;
    int t;
    if (warp < qtot) { v = qb + (size_t)warp * HD; w = qw; t = (warp / NH) % T_; }
    else { int wk2 = warp - qtot; v = kb + (size_t)wk2 * HD; w = kw; t = (wk2 / NKV) % T_; }

    float x0 = v[2 * lane], x1 = v[2 * lane + 1];
    float y0 = 0.f, y1 = 0.f;
    if (lane < 16) { y0 = v[64 + 2 * lane]; y1 = v[65 + 2 * lane]; }
    float ss = x0 * x0 + x1 * x1 + y0 * y0 + y1 * y1;
#pragma unroll
    for (int o = 16; o; o >>= 1) ss += __shfl_xor_sync(0xffffffffu, ss, o);
    float r = rsqrtf(ss / 96.f + 1e-6f);

    const float* cr = cs + t * HD;
    const float* sr = sn + t * HD;
    {
        int e0 = 2 * lane, e1 = e0 + 1;
        float a = x0 * w[e0] * r, b = x1 * w[e1] * r;
        v[e0] = a * cr[e0] - b * sr[e0];
        v[e1] = a * sr[e1] + b * cr[e1];
    }
    if (lane < 16) {
        int e0 = 64 + 2 * lane, e1 = e0 + 1;
        float a = y0 * w[e0] * r, b = y1 * w[e1] * r;
        v[e0] = a * cr[e0] - b * sr[e0];
        v[e1] = a * sr[e1] + b * cr[e1];
    }
}

// ---------------- Flash attention (tf32 mma.sync, Br=Bc=64) --------------------
// 128 threads = 4 warps; warp w owns rows w*16..w*16+15 of the 64-row q tile.
// Q: tf32 A-fragments in registers. K: smem [64][100]. V^T: smem [96][68].
// P: warp-private smem [64][68] round-trip between softmax and PV MMA.
#define FK_STR 100
#define FV_STR 68
#define FP_STR 68
#define F_SMEM_BYTES ((64 * FK_STR + 96 * FV_STR + 64 * FP_STR) * 4)

__global__ __launch_bounds__(128) void flash_tc(const float* __restrict__ Q,
                                                const float* __restrict__ K,
                                                const float* __restrict__ V,
                                                float* __restrict__ O) {
    extern __shared__ float sm[];
    float* Ks = sm;                 // [64][100]
    float* Vt = Ks + 64 * FK_STR;   // [96][68]  (d-major: Vt[d][kv])
    float* Ps = Vt + 96 * FV_STR;   // [64][68]

    const int qt = blockIdx.x;      // 0..15
    const int bh = blockIdx.y;      // b*32 + h
    const int b = bh >> 5, h = bh & 31, kvh = h >> 2;
    const int tid = threadIdx.x, lane = tid & 31, wid = tid >> 5;
    const int r = lane >> 2, c = lane & 3;
    const int row0 = wid * 16;
    const float scale = 0.10206207261596575f;  // 1/sqrt(96)

    // ---- load Q fragments (16 rows x 96), pre-scaled, tf32 --------------------
    const float* Qg = Q + ((size_t)(b * T_ + qt * 64 + row0) * NH + h) * HD;
    uint32_t qf[12][4];
#pragma unroll
    for (int kt = 0; kt < 12; kt++) {
        qf[kt][0] = f2tf32(Qg[(size_t)r * (NH * HD) + kt * 8 + c] * scale);
        qf[kt][1] = f2tf32(Qg[(size_t)(r + 8) * (NH * HD) + kt * 8 + c] * scale);
        qf[kt][2] = f2tf32(Qg[(size_t)r * (NH * HD) + kt * 8 + c + 4] * scale);
        qf[kt][3] = f2tf32(Qg[(size_t)(r + 8) * (NH * HD) + kt * 8 + c + 4] * scale);
    }

    float m0 = -1e30f, m1 = -1e30f, l0 = 0.f, l1 = 0.f;
    float oacc[12][4];
#pragma unroll
    for (int nt = 0; nt < 12; nt++)
#pragma unroll
        for (int j = 0; j < 4; j++) oacc[nt][j] = 0.f;

    const float* Kg = K + (size_t)b * T_ * NKV * HD + kvh * HD;
    const float* Vg = V + (size_t)b * T_ * NKV * HD + kvh * HD;

    for (int jt = 0; jt <= qt; jt++) {
        __syncthreads();  // previous Ks/Vt fully consumed
        // cooperative K (row-major) + V (transposed) load
        for (int i = tid; i < 64 * 24; i += 128) {
            int krow = i / 24, c4 = (i % 24) * 4;
            float4 vk = *(const float4*)(Kg + (size_t)(jt * 64 + krow) * (NKV * HD) + c4);
            *(float4*)(Ks + krow * FK_STR + c4) = vk;
            float4 vv = *(const float4*)(Vg + (size_t)(jt * 64 + krow) * (NKV * HD) + c4);
            Vt[(c4 + 0) * FV_STR + krow] = vv.x;
            Vt[(c4 + 1) * FV_STR + krow] = vv.y;
            Vt[(c4 + 2) * FV_STR + krow] = vv.z;
            Vt[(c4 + 3) * FV_STR + krow] = vv.w;
        }
        __syncthreads();

        // ---- S = Q @ K^T (warp: 16x64) ---------------------------------------
        float sacc[8][4];
#pragma unroll
        for (int nt = 0; nt < 8; nt++)
#pragma unroll
            for (int j = 0; j < 4; j++) sacc[nt][j] = 0.f;
#pragma unroll
        for (int kt = 0; kt < 12; kt++) {
#pragma unroll
            for (int nt = 0; nt < 8; nt++) {
                uint32_t bb[2];
                const float* p = Ks + (nt * 8 + r) * FK_STR + kt * 8 + c;
                bb[0] = f2tf32(p[0]);
                bb[1] = f2tf32(p[4]);
                mma16n8k8(sacc[nt], qf[kt], bb);
            }
        }

        // ---- causal mask on diagonal tile ------------------------------------
        if (jt == qt) {
            int grow = qt * 64 + row0 + r;
#pragma unroll
            for (int nt = 0; nt < 8; nt++) {
                int col = jt * 64 + nt * 8 + 2 * c;
                if (col > grow) sacc[nt][0] = -1e30f;
                if (col + 1 > grow) sacc[nt][1] = -1e30f;
                if (col > grow + 8) sacc[nt][2] = -1e30f;
                if (col + 1 > grow + 8) sacc[nt][3] = -1e30f;
            }
        }

        // ---- online softmax (rows r and r+8; quad = 4 lanes per row) ---------
        float tm0 = -1e30f, tm1 = -1e30f;
#pragma unroll
        for (int nt = 0; nt < 8; nt++) {
            tm0 = fmaxf(tm0, fmaxf(sacc[nt][0], sacc[nt][1]));
            tm1 = fmaxf(tm1, fmaxf(sacc[nt][2], sacc[nt][3]));
        }
        tm0 = fmaxf(tm0, __shfl_xor_sync(0xffffffffu, tm0, 1));
        tm0 = fmaxf(tm0, __shfl_xor_sync(0xffffffffu, tm0, 2));
        tm1 = fmaxf(tm1, __shfl_xor_sync(0xffffffffu, tm1, 1));
        tm1 = fmaxf(tm1, __shfl_xor_sync(0xffffffffu, tm1, 2));
        float nm0 = fmaxf(m0, tm0), nm1 = fmaxf(m1, tm1);
        float al0 = __expf(m0 - nm0), al1 = __expf(m1 - nm1);
        m0 = nm0; m1 = nm1;
        float rs0 = 0.f, rs1 = 0.f;
#pragma unroll
        for (int nt = 0; nt < 8; nt++) {
            float p0 = __expf(sacc[nt][0] - nm0);
            float p1 = __expf(sacc[nt][1] - nm0);
            float p2 = __expf(sacc[nt][2] - nm1);
            float p3 = __expf(sacc[nt][3] - nm1);
            rs0 += p0 + p1;
            rs1 += p2 + p3;
            *(float2*)(Ps + (row0 + r) * FP_STR + nt * 8 + 2 * c) = make_float2(p0, p1);
            *(float2*)(Ps + (row0 + r + 8) * FP_STR + nt * 8 + 2 * c) = make_float2(p2, p3);
        }
        rs0 += __shfl_xor_sync(0xffffffffu, rs0, 1);
        rs0 += __shfl_xor_sync(0xffffffffu, rs0, 2);
        rs1 += __shfl_xor_sync(0xffffffffu, rs1, 1);
        rs1 += __shfl_xor_sync(0xffffffffu, rs1, 2);
        l0 = l0 * al0 + rs0;
        l1 = l1 * al1 + rs1;
#pragma unroll
        for (int nt = 0; nt < 12; nt++) {
            oacc[nt][0] *= al0; oacc[nt][1] *= al0;
            oacc[nt][2] *= al1; oacc[nt][3] *= al1;
        }
        __syncwarp();  // Ps stores visible to all lanes of this warp

        // ---- O += P @ V (warp: 16x96) ----------------------------------------
#pragma unroll
        for (int k8 = 0; k8 < 8; k8++) {
            uint32_t af[4];
            af[0] = f2tf32(Ps[(row0 + r) * FP_STR + k8 * 8 + c]);
            af[1] = f2tf32(Ps[(row0 + r + 8) * FP_STR + k8 * 8 + c]);
            af[2] = f2tf32(Ps[(row0 + r) * FP_STR + k8 * 8 + c + 4]);
            af[3] = f2tf32(Ps[(row0 + r + 8) * FP_STR + k8 * 8 + c + 4]);
#pragma unroll
            for (int nt = 0; nt < 12; nt++) {
                uint32_t bb[2];
                const float* p = Vt + (nt * 8 + r) * FV_STR + k8 * 8 + c;
                bb[0] = f2tf32(p[0]);
                bb[1] = f2tf32(p[4]);
                mma16n8k8(oacc[nt], af, bb);
            }
        }
    }

    // ---- epilogue -------------------------------------------------------------
    float inv0 = 1.f / l0, inv1 = 1.f / l1;
    float* Og0 = O + ((size_t)(b * T_ + qt * 64 + row0 + r) * NH + h) * HD;
    float* Og1 = O + ((size_t)(b * T_ + qt * 64 + row0 + r + 8) * NH + h) * HD;
#pragma unroll
    for (int nt = 0; nt < 12; nt++) {
        *(float2*)(Og0 + nt * 8 + 2 * c) = make_float2(oacc[nt][0] * inv0, oacc[nt][1] * inv0);
        *(float2*)(Og1 + nt * 8 + 2 * c) = make_float2(oacc[nt][2] * inv1, oacc[nt][3] * inv1);
    }
}

// ---------------- launch -------------------------------------------------------
extern "C" void kernel_launch(void* const* d_in, const int* in_sizes, int n_in,
                              void* d_out, int out_size) {
    const float* x   = (const float*)d_in[0];
    const float* wq  = (const float*)d_in[2];
    const float* wk  = (const float*)d_in[3];
    const float* wv  = (const float*)d_in[4];
    const float* wo  = (const float*)d_in[5];
    const float* qnw = (const float*)d_in[6];
    const float* knw = (const float*)d_in[7];
    const float* cs  = (const float*)d_in[8];
    const float* sn  = (const float*)d_in[9];
    float* out = (float*)d_out;

    float *q_buf, *k_buf, *v_buf, *o_buf;
    cudaGetSymbolAddress((void**)&q_buf, g_q);
    cudaGetSymbolAddress((void**)&k_buf, g_k);
    cudaGetSymbolAddress((void**)&v_buf, g_v);
    cudaGetSymbolAddress((void**)&o_buf, g_o);

    const int M = B_ * T_;  // 2048

    cudaFuncSetAttribute(gemm_qkv, cudaFuncAttributeMaxDynamicSharedMemorySize, G_SMEM_BYTES);
    cudaFuncSetAttribute(gemm_tf32, cudaFuncAttributeMaxDynamicSharedMemorySize, G_SMEM_BYTES);
    cudaFuncSetAttribute(flash_tc, cudaFuncAttributeMaxDynamicSharedMemorySize, F_SMEM_BYTES);

    // fused QKV projection: 36 x 16 = 576 blocks
    {
        dim3 g((DM + 2 * NKV * HD) / 128, M / 128);
        gemm_qkv<<<g, 256, G_SMEM_BYTES>>>(x, wq, wk, wv, q_buf, k_buf, v_buf);
    }

    // fused RMSNorm + RoPE (Q and K in one launch)
    {
        int warps = M * NH + M * NKV;
        norm_rope_fused<<<(warps * 32 + 255) / 256, 256>>>(q_buf, k_buf, qnw, knw, cs, sn);
    }

    // flash attention (tf32 mma.sync)
    {
        dim3 grid(T_ / 64, B_ * NH);
        flash_tc<<<grid, 128, F_SMEM_BYTES>>>(q_buf, k_buf, v_buf, o_buf);
    }

    // output projection
    dim3 go(DM / 128, M / 128);
    gemm_tf32<<<go, 256, G_SMEM_BYTES>>>(o_buf, wo, out, DM, DM);
}

// round 15
// speedup vs baseline: 3.4091x; 1.0264x over previous
#include <cuda_runtime.h>
#include <cuda_bf16.h>
#include <math.h>
#include <cstdint>

#define B_ 2
#define T_ 1024
#define DM 3072
#define NH 32
#define NKV 8
#define HD 96

// ---------------- scratch (device globals; no allocation allowed) --------------
__device__ float g_q[B_ * T_ * NH * HD];    // [bt][h][d]
__device__ float g_k[B_ * T_ * NKV * HD];   // [bt][kvh][d]
__device__ float g_v[B_ * T_ * NKV * HD];
__device__ float g_o[B_ * T_ * NH * HD];    // attention output (pre-rounded tf32)
// pre-rounded tf32 copies of GEMM operands
__device__ float g_xr[B_ * T_ * DM];
__device__ float g_wqr[NH * HD * DM];
__device__ float g_wkr[NKV * HD * DM];
__device__ float g_wvr[NKV * HD * DM];
__device__ float g_wor[DM * NH * HD];

// ================= PTX helpers (baseline ISA only — no sm_103a features) =======
__device__ __forceinline__ uint32_t smem_u32(const void* p) {
    uint32_t a;
    asm("{ .reg .u64 t; cvta.to.shared.u64 t, %1; cvt.u32.u64 %0, t; }" : "=r"(a) : "l"(p));
    return a;
}
#define CP_ASYNC16(dst, src) \
    asm volatile("cp.async.cg.shared.global [%0], [%1], 16;" :: "r"(dst), "l"(src))
#define CP_COMMIT() asm volatile("cp.async.commit_group;" ::: "memory")
#define CP_WAIT(n)  asm volatile("cp.async.wait_group %0;" :: "n"(n) : "memory")

__device__ __forceinline__ uint32_t f2tf32(float f) {
    uint32_t u;
    asm("cvt.rna.tf32.f32 %0, %1;" : "=r"(u) : "f"(f));
    return u;
}
__device__ __forceinline__ void mma16n8k8(float* d, const uint32_t* a, const uint32_t* b) {
    asm volatile(
        "mma.sync.aligned.m16n8k8.row.col.f32.tf32.tf32.f32 "
        "{%0,%1,%2,%3}, {%4,%5,%6,%7}, {%8,%9}, {%0,%1,%2,%3};"
        : "+f"(d[0]), "+f"(d[1]), "+f"(d[2]), "+f"(d[3])
        : "r"(a[0]), "r"(a[1]), "r"(a[2]), "r"(a[3]), "r"(b[0]), "r"(b[1]));
}

// ---------------- pre-round to canonical tf32 (elementwise, float4) ------------
__global__ void round_tf32(const float* __restrict__ src, float* __restrict__ dst, int n4) {
    int i = blockIdx.x * blockDim.x + threadIdx.x;
    if (i >= n4) return;
    float4 v = ((const float4*)src)[i];
    uint4 u;
    u.x = f2tf32(v.x); u.y = f2tf32(v.y); u.z = f2tf32(v.z); u.w = f2tf32(v.w);
    ((uint4*)dst)[i] = u;
}

// ================= tf32 mma.sync GEMM core (operands pre-rounded) ==============
// 128x128x32 block tile, 256 threads (8 warps, 2x4), warp tile 64x32.
// smem: 2 stages x (As[128][36] + Bs[128][36]) floats, cp.async double buffer.
// NOTE: A and B must already be canonical tf32 — fragments are loaded as raw bits.
#define GK 32
#define G_PAD 36
#define G_STAGE_FLOATS (2 * 128 * G_PAD)
#define G_SMEM_BYTES (2 * G_STAGE_FLOATS * 4)

__device__ __forceinline__ void gemm_core(const float* __restrict__ A,
                                          const float* __restrict__ Bm,
                                          float* __restrict__ C,
                                          int N, int K, int bm, int bn,
                                          float* gsm) {
    const int tid = threadIdx.x;
    const int lane = tid & 31, wid = tid >> 5;
    const int wm = wid & 1, wn = wid >> 1;        // warp grid 2(m) x 4(n)
    const int m0 = wm * 64, n0 = wn * 32;

    const int lrow = tid >> 3;
    const int lc4 = (tid & 7) * 4;
    const uint32_t smem_base = smem_u32(gsm);

    const float* Ag = A + (size_t)(bm + lrow) * K + lc4;
    const float* Bg = Bm + (size_t)(bn + lrow) * K + lc4;

    float acc[4][4][4];
#pragma unroll
    for (int mt = 0; mt < 4; mt++)
#pragma unroll
        for (int nt = 0; nt < 4; nt++)
#pragma unroll
            for (int r = 0; r < 4; r++) acc[mt][nt][r] = 0.f;

    const int nch = K / GK;

    auto load_chunk = [&](int k, int s) {
        uint32_t sa = smem_base + (uint32_t)s * (G_STAGE_FLOATS * 4);
        uint32_t sb = sa + 128 * G_PAD * 4;
        const float* ag = Ag + (size_t)k * GK;
        const float* bg = Bg + (size_t)k * GK;
#pragma unroll
        for (int i = 0; i < 4; i++) {
            uint32_t off = (uint32_t)(lrow + i * 32) * (G_PAD * 4) + lc4 * 4;
            CP_ASYNC16(sa + off, ag + (size_t)(i * 32) * K);
            CP_ASYNC16(sb + off, bg + (size_t)(i * 32) * K);
        }
    };

    load_chunk(0, 0);
    CP_COMMIT();

    const int a_r = lane >> 2, a_c = lane & 3;

    for (int k = 0; k < nch; k++) {
        if (k + 1 < nch) {
            load_chunk(k + 1, (k + 1) & 1);
            CP_COMMIT();
            CP_WAIT(1);
        } else {
            CP_WAIT(0);
        }
        __syncthreads();

        const uint32_t* As = (const uint32_t*)(gsm + (k & 1) * G_STAGE_FLOATS);
        const uint32_t* Bs = As + 128 * G_PAD;

#pragma unroll
        for (int ks = 0; ks < 4; ks++) {
            uint32_t af[4][4], bf[4][2];
#pragma unroll
            for (int mt = 0; mt < 4; mt++) {
                const uint32_t* p = As + (m0 + mt * 16 + a_r) * G_PAD + ks * 8 + a_c;
                af[mt][0] = p[0];
                af[mt][1] = p[8 * G_PAD];
                af[mt][2] = p[4];
                af[mt][3] = p[8 * G_PAD + 4];
            }
#pragma unroll
            for (int nt = 0; nt < 4; nt++) {
                const uint32_t* p = Bs + (n0 + nt * 8 + a_r) * G_PAD + ks * 8 + a_c;
                bf[nt][0] = p[0];
                bf[nt][1] = p[4];
            }
#pragma unroll
            for (int mt = 0; mt < 4; mt++)
#pragma unroll
                for (int nt = 0; nt < 4; nt++)
                    mma16n8k8(acc[mt][nt], af[mt], bf[nt]);
        }
        __syncthreads();
    }

#pragma unroll
    for (int mt = 0; mt < 4; mt++) {
        int r_lo = bm + m0 + mt * 16 + a_r;
#pragma unroll
        for (int nt = 0; nt < 4; nt++) {
            int col = bn + n0 + nt * 8 + 2 * a_c;
            *(float2*)(C + (size_t)r_lo * N + col) = make_float2(acc[mt][nt][0], acc[mt][nt][1]);
            *(float2*)(C + (size_t)(r_lo + 8) * N + col) = make_float2(acc[mt][nt][2], acc[mt][nt][3]);
        }
    }
}

__global__ __launch_bounds__(256) void gemm_tf32(const float* __restrict__ A,
                                                 const float* __restrict__ Bm,
                                                 float* __restrict__ C,
                                                 int N, int K) {
    extern __shared__ float gsm[];
    gemm_core(A, Bm, C, N, K, blockIdx.y * 128, blockIdx.x * 128, gsm);
}

// fused QKV projection over N_total = 3072+768+768 = 4608
__global__ __launch_bounds__(256) void gemm_qkv(const float* __restrict__ x,
                                                const float* __restrict__ wq,
                                                const float* __restrict__ wk,
                                                const float* __restrict__ wv,
                                                float* __restrict__ qb,
                                                float* __restrict__ kb,
                                                float* __restrict__ vb) {
    extern __shared__ float gsm[];
    int bn = blockIdx.x * 128;
    const float* Bsrc;
    float* Cdst;
    int Nc, bnl;
    if (bn < 3072)      { Bsrc = wq; Cdst = qb; Nc = 3072; bnl = bn; }
    else if (bn < 3840) { Bsrc = wk; Cdst = kb; Nc = 768;  bnl = bn - 3072; }
    else                { Bsrc = wv; Cdst = vb; Nc = 768;  bnl = bn - 3840; }
    gemm_core(x, Bsrc, Cdst, Nc, DM, blockIdx.y * 128, bnl, gsm);
}

// ---------------- fused RMSNorm + RoPE (one warp per head-vector) --------------
__global__ void norm_rope_fused(float* __restrict__ qb, float* __restrict__ kb,
                                const float* __restrict__ qw, const float* __restrict__ kw,
                                const float* __restrict__ cs, const float* __restrict__ sn) {
    int warp = (blockIdx.x * blockDim.x + threadIdx.x) >> 5;
    int lane = threadIdx.x & 31;
    const int qtot = B_ * T_ * NH;
    const int ktot = B_ * T_ * NKV;
    if (warp >= qtot + ktot) return;
    float* v;
    const float* w;
    int t;
    if (warp < qtot) { v = qb + (size_t)warp * HD; w = qw; t = (warp / NH) % T_; }
    else { int wk2 = warp - qtot; v = kb + (size_t)wk2 * HD; w = kw; t = (wk2 / NKV) % T_; }

    float x0 = v[2 * lane], x1 = v[2 * lane + 1];
    float y0 = 0.f, y1 = 0.f;
    if (lane < 16) { y0 = v[64 + 2 * lane]; y1 = v[65 + 2 * lane]; }
    float ss = x0 * x0 + x1 * x1 + y0 * y0 + y1 * y1;
#pragma unroll
    for (int o = 16; o; o >>= 1) ss += __shfl_xor_sync(0xffffffffu, ss, o);
    float r = rsqrtf(ss / 96.f + 1e-6f);

    const float* cr = cs + t * HD;
    const float* sr = sn + t * HD;
    {
        int e0 = 2 * lane, e1 = e0 + 1;
        float a = x0 * w[e0] * r, b = x1 * w[e1] * r;
        v[e0] = a * cr[e0] - b * sr[e0];
        v[e1] = a * sr[e1] + b * cr[e1];
    }
    if (lane < 16) {
        int e0 = 64 + 2 * lane, e1 = e0 + 1;
        float a = y0 * w[e0] * r, b = y1 * w[e1] * r;
        v[e0] = a * cr[e0] - b * sr[e0];
        v[e1] = a * sr[e1] + b * cr[e1];
    }
}

// ---------------- Flash attention (tf32 mma.sync, Br=Bc=64) --------------------
#define FK_STR 100
#define FV_STR 68
#define FP_STR 68
#define F_SMEM_BYTES ((64 * FK_STR + 96 * FV_STR + 64 * FP_STR) * 4)

__global__ __launch_bounds__(128) void flash_tc(const float* __restrict__ Q,
                                                const float* __restrict__ K,
                                                const float* __restrict__ V,
                                                float* __restrict__ O) {
    extern __shared__ float sm[];
    float* Ks = sm;                 // [64][100]
    float* Vt = Ks + 64 * FK_STR;   // [96][68]  (d-major: Vt[d][kv])
    float* Ps = Vt + 96 * FV_STR;   // [64][68]

    const int qt = blockIdx.x;      // 0..15
    const int bh = blockIdx.y;      // b*32 + h
    const int b = bh >> 5, h = bh & 31, kvh = h >> 2;
    const int tid = threadIdx.x, lane = tid & 31, wid = tid >> 5;
    const int r = lane >> 2, c = lane & 3;
    const int row0 = wid * 16;
    const float scale = 0.10206207261596575f;  // 1/sqrt(96)

    const float* Qg = Q + ((size_t)(b * T_ + qt * 64 + row0) * NH + h) * HD;
    uint32_t qf[12][4];
#pragma unroll
    for (int kt = 0; kt < 12; kt++) {
        qf[kt][0] = f2tf32(Qg[(size_t)r * (NH * HD) + kt * 8 + c] * scale);
        qf[kt][1] = f2tf32(Qg[(size_t)(r + 8) * (NH * HD) + kt * 8 + c] * scale);
        qf[kt][2] = f2tf32(Qg[(size_t)r * (NH * HD) + kt * 8 + c + 4] * scale);
        qf[kt][3] = f2tf32(Qg[(size_t)(r + 8) * (NH * HD) + kt * 8 + c + 4] * scale);
    }

    float m0 = -1e30f, m1 = -1e30f, l0 = 0.f, l1 = 0.f;
    float oacc[12][4];
#pragma unroll
    for (int nt = 0; nt < 12; nt++)
#pragma unroll
        for (int j = 0; j < 4; j++) oacc[nt][j] = 0.f;

    const float* Kg = K + (size_t)b * T_ * NKV * HD + kvh * HD;
    const float* Vg = V + (size_t)b * T_ * NKV * HD + kvh * HD;

    for (int jt = 0; jt <= qt; jt++) {
        __syncthreads();
        for (int i = tid; i < 64 * 24; i += 128) {
            int krow = i / 24, c4 = (i % 24) * 4;
            float4 vk = *(const float4*)(Kg + (size_t)(jt * 64 + krow) * (NKV * HD) + c4);
            *(float4*)(Ks + krow * FK_STR + c4) = vk;
            float4 vv = *(const float4*)(Vg + (size_t)(jt * 64 + krow) * (NKV * HD) + c4);
            Vt[(c4 + 0) * FV_STR + krow] = vv.x;
            Vt[(c4 + 1) * FV_STR + krow] = vv.y;
            Vt[(c4 + 2) * FV_STR + krow] = vv.z;
            Vt[(c4 + 3) * FV_STR + krow] = vv.w;
        }
        __syncthreads();

        float sacc[8][4];
#pragma unroll
        for (int nt = 0; nt < 8; nt++)
#pragma unroll
            for (int j = 0; j < 4; j++) sacc[nt][j] = 0.f;
#pragma unroll
        for (int kt = 0; kt < 12; kt++) {
#pragma unroll
            for (int nt = 0; nt < 8; nt++) {
                uint32_t bb[2];
                const float* p = Ks + (nt * 8 + r) * FK_STR + kt * 8 + c;
                bb[0] = f2tf32(p[0]);
                bb[1] = f2tf32(p[4]);
                mma16n8k8(sacc[nt], qf[kt], bb);
            }
        }

        if (jt == qt) {
            int grow = qt * 64 + row0 + r;
#pragma unroll
            for (int nt = 0; nt < 8; nt++) {
                int col = jt * 64 + nt * 8 + 2 * c;
                if (col > grow) sacc[nt][0] = -1e30f;
                if (col + 1 > grow) sacc[nt][1] = -1e30f;
                if (col > grow + 8) sacc[nt][2] = -1e30f;
                if (col + 1 > grow + 8) sacc[nt][3] = -1e30f;
            }
        }

        float tm0 = -1e30f, tm1 = -1e30f;
#pragma unroll
        for (int nt = 0; nt < 8; nt++) {
            tm0 = fmaxf(tm0, fmaxf(sacc[nt][0], sacc[nt][1]));
            tm1 = fmaxf(tm1, fmaxf(sacc[nt][2], sacc[nt][3]));
        }
        tm0 = fmaxf(tm0, __shfl_xor_sync(0xffffffffu, tm0, 1));
        tm0 = fmaxf(tm0, __shfl_xor_sync(0xffffffffu, tm0, 2));
        tm1 = fmaxf(tm1, __shfl_xor_sync(0xffffffffu, tm1, 1));
        tm1 = fmaxf(tm1, __shfl_xor_sync(0xffffffffu, tm1, 2));
        float nm0 = fmaxf(m0, tm0), nm1 = fmaxf(m1, tm1);
        float al0 = __expf(m0 - nm0), al1 = __expf(m1 - nm1);
        m0 = nm0; m1 = nm1;
        float rs0 = 0.f, rs1 = 0.f;
#pragma unroll
        for (int nt = 0; nt < 8; nt++) {
            float p0 = __expf(sacc[nt][0] - nm0);
            float p1 = __expf(sacc[nt][1] - nm0);
            float p2 = __expf(sacc[nt][2] - nm1);
            float p3 = __expf(sacc[nt][3] - nm1);
            rs0 += p0 + p1;
            rs1 += p2 + p3;
            *(float2*)(Ps + (row0 + r) * FP_STR + nt * 8 + 2 * c) = make_float2(p0, p1);
            *(float2*)(Ps + (row0 + r + 8) * FP_STR + nt * 8 + 2 * c) = make_float2(p2, p3);
        }
        rs0 += __shfl_xor_sync(0xffffffffu, rs0, 1);
        rs0 += __shfl_xor_sync(0xffffffffu, rs0, 2);
        rs1 += __shfl_xor_sync(0xffffffffu, rs1, 1);
        rs1 += __shfl_xor_sync(0xffffffffu, rs1, 2);
        l0 = l0 * al0 + rs0;
        l1 = l1 * al1 + rs1;
#pragma unroll
        for (int nt = 0; nt < 12; nt++) {
            oacc[nt][0] *= al0; oacc[nt][1] *= al0;
            oacc[nt][2] *= al1; oacc[nt][3] *= al1;
        }
        __syncwarp();

#pragma unroll
        for (int k8 = 0; k8 < 8; k8++) {
            uint32_t af[4];
            af[0] = f2tf32(Ps[(row0 + r) * FP_STR + k8 * 8 + c]);
            af[1] = f2tf32(Ps[(row0 + r + 8) * FP_STR + k8 * 8 + c]);
            af[2] = f2tf32(Ps[(row0 + r) * FP_STR + k8 * 8 + c + 4]);
            af[3] = f2tf32(Ps[(row0 + r + 8) * FP_STR + k8 * 8 + c + 4]);
#pragma unroll
            for (int nt = 0; nt < 12; nt++) {
                uint32_t bb[2];
                const float* p = Vt + (nt * 8 + r) * FV_STR + k8 * 8 + c;
                bb[0] = f2tf32(p[0]);
                bb[1] = f2tf32(p[4]);
                mma16n8k8(oacc[nt], af, bb);
            }
        }
    }

    // epilogue — store PRE-ROUNDED tf32 (feeds the O-projection GEMM directly)
    float inv0 = 1.f / l0, inv1 = 1.f / l1;
    float* Og0 = O + ((size_t)(b * T_ + qt * 64 + row0 + r) * NH + h) * HD;
    float* Og1 = O + ((size_t)(b * T_ + qt * 64 + row0 + r + 8) * NH + h) * HD;
#pragma unroll
    for (int nt = 0; nt < 12; nt++) {
        *(uint2*)(Og0 + nt * 8 + 2 * c) = make_uint2(f2tf32(oacc[nt][0] * inv0), f2tf32(oacc[nt][1] * inv0));
        *(uint2*)(Og1 + nt * 8 + 2 * c) = make_uint2(f2tf32(oacc[nt][2] * inv1), f2tf32(oacc[nt][3] * inv1));
    }
}

// ---------------- launch -------------------------------------------------------
extern "C" void kernel_launch(void* const* d_in, const int* in_sizes, int n_in,
                              void* d_out, int out_size) {
    const float* x   = (const float*)d_in[0];
    const float* wq  = (const float*)d_in[2];
    const float* wk  = (const float*)d_in[3];
    const float* wv  = (const float*)d_in[4];
    const float* wo  = (const float*)d_in[5];
    const float* qnw = (const float*)d_in[6];
    const float* knw = (const float*)d_in[7];
    const float* cs  = (const float*)d_in[8];
    const float* sn  = (const float*)d_in[9];
    float* out = (float*)d_out;

    float *q_buf, *k_buf, *v_buf, *o_buf;
    float *xr, *wqr, *wkr, *wvr, *wor;
    cudaGetSymbolAddress((void**)&q_buf, g_q);
    cudaGetSymbolAddress((void**)&k_buf, g_k);
    cudaGetSymbolAddress((void**)&v_buf, g_v);
    cudaGetSymbolAddress((void**)&o_buf, g_o);
    cudaGetSymbolAddress((void**)&xr, g_xr);
    cudaGetSymbolAddress((void**)&wqr, g_wqr);
    cudaGetSymbolAddress((void**)&wkr, g_wkr);
    cudaGetSymbolAddress((void**)&wvr, g_wvr);
    cudaGetSymbolAddress((void**)&wor, g_wor);

    const int M = B_ * T_;  // 2048

    cudaFuncSetAttribute(gemm_qkv, cudaFuncAttributeMaxDynamicSharedMemorySize, G_SMEM_BYTES);
    cudaFuncSetAttribute(gemm_tf32, cudaFuncAttributeMaxDynamicSharedMemorySize, G_SMEM_BYTES);
    cudaFuncSetAttribute(flash_tc, cudaFuncAttributeMaxDynamicSharedMemorySize, F_SMEM_BYTES);

    // pre-round all GEMM operands to canonical tf32
    {
        auto rr = [&](const float* s, float* d, int n) {
            int n4 = n / 4;
            round_tf32<<<(n4 + 255) / 256, 256>>>(s, d, n4);
        };
        rr(x, xr, M * DM);
        rr(wq, wqr, NH * HD * DM);
        rr(wk, wkr, NKV * HD * DM);
        rr(wv, wvr, NKV * HD * DM);
        rr(wo, wor, DM * NH * HD);
    }

    // fused QKV projection: 36 x 16 = 576 blocks
    {
        dim3 g((DM + 2 * NKV * HD) / 128, M / 128);
        gemm_qkv<<<g, 256, G_SMEM_BYTES>>>(xr, wqr, wkr, wvr, q_buf, k_buf, v_buf);
    }

    // fused RMSNorm + RoPE (Q and K in one launch)
    {
        int warps = M * NH + M * NKV;
        norm_rope_fused<<<(warps * 32 + 255) / 256, 256>>>(q_buf, k_buf, qnw, knw, cs, sn);
    }

    // flash attention (tf32 mma.sync; writes pre-rounded O)
    {
        dim3 grid(T_ / 64, B_ * NH);
        flash_tc<<<grid, 128, F_SMEM_BYTES>>>(q_buf, k_buf, v_buf, o_buf);
    }

    // output projection (o_buf already tf32-canonical from flash epilogue)
    dim3 go(DM / 128, M / 128);
    gemm_tf32<<<go, 256, G_SMEM_BYTES>>>(o_buf, wor, out, DM, DM);
}